// round 3
// baseline (speedup 1.0000x reference)
#include <cuda_runtime.h>
#include <cuda_bf16.h>
#include <cstdint>

#define NROWS   65536       // 4*2048*8 query rows
#define D       256
#define SUB     128
#define NC      1024
#define KOUT    16
#define TM      16          // rows per gemm block
#define THREADS 256
#define NEG_BIG (-3.0e38f)

// smem layout (bytes)
#define CT_FLOATS_PER_BUF (16 * 1024)            // 16 k x 1024 cols
#define OFF_CT  0
#define OFF_QN  (2 * CT_FLOATS_PER_BUF * 4)      // 131072
#define OFF_SC  (OFF_QN + TM * SUB * 2 * 4)      // 147456 (qn duplicated {q,q})
#define SMEM_BYTES (OFF_SC + TM * NC * 4)        // 212992

// scratch: k-major transposed centroid matrices + per-subspace tops
__device__ float g_ct[2][SUB][NC];               // 1 MB
__device__ float g_tv[2][NROWS * KOUT];
__device__ int   g_ti[2][NROWS * KOUT];

__device__ __forceinline__ void cp_async16(void* dst, const void* src) {
    uint32_t d32 = (uint32_t)__cvta_generic_to_shared(dst);
    asm volatile("cp.async.cg.shared.global [%0], [%1], 16;" :: "r"(d32), "l"(src));
}
__device__ __forceinline__ void fma2(unsigned long long& d,
                                     unsigned long long a,
                                     unsigned long long b) {
    asm("fma.rn.f32x2 %0, %1, %2, %0;" : "+l"(d) : "l"(a), "l"(b));
}

// ---------------------------------------------------------------------------
// Kernel 0: transpose C[1024][128] -> g_ct[m][128][1024]
// ---------------------------------------------------------------------------
__global__ __launch_bounds__(256)
void pkr_transpose(const float* __restrict__ ck, const float* __restrict__ cpk)
{
    __shared__ float ts[32][33];
    const int m  = blockIdx.z;
    const int k0 = blockIdx.x * 32;
    const int n0 = blockIdx.y * 32;
    const int tx = threadIdx.x, ty = threadIdx.y;   // block (32,8)
    const float* C = m ? cpk : ck;

    #pragma unroll
    for (int j = 0; j < 4; j++)
        ts[ty + 8 * j][tx] = C[(n0 + ty + 8 * j) * SUB + k0 + tx];
    __syncthreads();
    #pragma unroll
    for (int j = 0; j < 4; j++)
        g_ct[m][k0 + ty + 8 * j][n0 + tx] = ts[tx][ty + 8 * j];
}

// ---------------------------------------------------------------------------
// Kernel 1: LN + per-subspace GEMM (16 x 1024 x 128, f32x2) + top-16 of 1024
// grid = 8192: blockIdx>>1 = row tile, blockIdx&1 = subspace
// ---------------------------------------------------------------------------
__global__ __launch_bounds__(THREADS, 1)
void pkr_gemm(const float* __restrict__ q,
              const float* __restrict__ gamma,
              const float* __restrict__ beta)
{
    extern __shared__ char smraw[];
    float* ct  = (float*)(smraw + OFF_CT);
    float* qn2 = (float*)(smraw + OFF_QN);   // [row][k] duplicated pairs
    float* sc  = (float*)(smraw + OFF_SC);

    const int tx   = threadIdx.x;
    const int warp = tx >> 5;
    const int lane = tx & 31;
    const int m    = blockIdx.x & 1;
    const long base = (long)(blockIdx.x >> 1) * TM;

    // ---- prefetch one 16k x 1024col tile (contiguous 64 KB)
    auto prefetch = [&](int t, int buf) {
        const float* src = &g_ct[m][t * 16][0];
        float* dst = ct + buf * CT_FLOATS_PER_BUF;
        #pragma unroll
        for (int i = 0; i < 16; i++) {
            int e = (tx + 256 * i) * 4;
            cp_async16(dst + e, src + e);
        }
        asm volatile("cp.async.commit_group;");
    };

    prefetch(0, 0);

    // ---- LayerNorm (warp w: rows 2w, 2w+1), keep our 128-half, duplicated
    #pragma unroll
    for (int rr = 0; rr < 2; rr++) {
        int row = warp * 2 + rr;
        const float* qrow = q + (base + row) * D;
        float v[8];
        float s = 0.f, s2 = 0.f;
        #pragma unroll
        for (int i = 0; i < 8; i++) {
            v[i] = qrow[lane + 32 * i];
            s  += v[i];
            s2 += v[i] * v[i];
        }
        #pragma unroll
        for (int o = 16; o; o >>= 1) {
            s  += __shfl_xor_sync(0xffffffffu, s,  o);
            s2 += __shfl_xor_sync(0xffffffffu, s2, o);
        }
        float mu  = s * (1.f / D);
        float var = s2 * (1.f / D) - mu * mu;
        float inv = rsqrtf(var + 1e-5f);
        #pragma unroll
        for (int i = 0; i < 4; i++) {
            int ig = i + 4 * m;             // d = lane + 32*ig
            int d  = lane + 32 * ig;
            float val = (v[ig] - mu) * inv * gamma[d] + beta[d];
            int kl = d - m * SUB;           // local k in [0,128)
            qn2[row * 256 + 2 * kl]     = val;
            qn2[row * 256 + 2 * kl + 1] = val;
        }
    }

    // ---- GEMM: thread tile 8 rows x 8 cols, packed f32x2 accumulators
    const int c_g = tx & 127;               // cols 8*c_g .. 8*c_g+7
    const int r_g = tx >> 7;                // rows 8*r_g .. 8*r_g+7

    unsigned long long acc[8][4];
    #pragma unroll
    for (int r = 0; r < 8; r++)
        #pragma unroll
        for (int j = 0; j < 4; j++) acc[r][j] = 0ull;

    for (int t = 0; t < 8; t++) {
        if (t < 7) {
            prefetch(t + 1, (t + 1) & 1);
            asm volatile("cp.async.wait_group 1;");
        } else {
            asm volatile("cp.async.wait_group 0;");
        }
        __syncthreads();

        const float* ctb = ct + (t & 1) * CT_FLOATS_PER_BUF;
        const int kg0 = t * 16;

        #pragma unroll
        for (int kl = 0; kl < 16; kl += 2) {
            unsigned long long q0[8], q1[8];
            #pragma unroll
            for (int r = 0; r < 8; r++) {
                ulonglong2 qq = *(const ulonglong2*)
                    &qn2[(8 * r_g + r) * 256 + 2 * (kg0 + kl)];
                q0[r] = qq.x;  q1[r] = qq.y;
            }
            #pragma unroll
            for (int s = 0; s < 2; s++) {
                ulonglong2 ca = *(const ulonglong2*)&ctb[(kl + s) * NC + 8 * c_g];
                ulonglong2 cb = *(const ulonglong2*)&ctb[(kl + s) * NC + 8 * c_g + 4];
                #pragma unroll
                for (int r = 0; r < 8; r++) {
                    unsigned long long qv = s ? q1[r] : q0[r];
                    fma2(acc[r][0], qv, ca.x);
                    fma2(acc[r][1], qv, ca.y);
                    fma2(acc[r][2], qv, cb.x);
                    fma2(acc[r][3], qv, cb.y);
                }
            }
        }
        __syncthreads();
    }

    // ---- write scores (packed pairs are little-endian: low 32 = even col)
    #pragma unroll
    for (int r = 0; r < 8; r++) {
        *(ulonglong2*)&sc[(8 * r_g + r) * NC + 8 * c_g]     =
            make_ulonglong2(acc[r][0], acc[r][1]);
        *(ulonglong2*)&sc[(8 * r_g + r) * NC + 8 * c_g + 4] =
            make_ulonglong2(acc[r][2], acc[r][3]);
    }
    __syncthreads();

    // ---- per-row top-16 of 1024 (warp w: rows 2w, 2w+1)
    for (int rr = 0; rr < 2; rr++) {
        int row = warp * 2 + rr;
        float v[32];
        #pragma unroll
        for (int i = 0; i < 32; i++)
            v[i] = sc[row * NC + lane + 32 * i];

        float bmax = v[0];
        int   bidx = 0;
        #pragma unroll
        for (int i = 1; i < 32; i++)
            if (v[i] > bmax) { bmax = v[i]; bidx = i; }

        long gb = (base + row) * KOUT;
        for (int r16 = 0; r16 < 16; r16++) {
            float wv = bmax;
            int   wi = lane + bidx * 32;
            #pragma unroll
            for (int o = 16; o; o >>= 1) {
                float ov = __shfl_xor_sync(0xffffffffu, wv, o);
                int   oi = __shfl_xor_sync(0xffffffffu, wi, o);
                if (ov > wv || (ov == wv && oi < wi)) { wv = ov; wi = oi; }
            }
            if (lane == 0) { g_tv[m][gb + r16] = wv; g_ti[m][gb + r16] = wi; }
            if ((wi & 31) == lane) v[wi >> 5] = NEG_BIG;
            bmax = v[0]; bidx = 0;
            #pragma unroll
            for (int i = 1; i < 32; i++)
                if (v[i] > bmax) { bmax = v[i]; bidx = i; }
        }
    }
}

// ---------------------------------------------------------------------------
// Kernel 2: joint 16x16 top-16 + output. 8 rows/block, 1 row per warp.
// ---------------------------------------------------------------------------
__global__ __launch_bounds__(THREADS, 1)
void pkr_joint(float* __restrict__ out)
{
    __shared__ float s1v[8 * KOUT], s2v[8 * KOUT];
    __shared__ int   s1i[8 * KOUT], s2i[8 * KOUT];

    const int tx   = threadIdx.x;
    const int warp = tx >> 5;
    const int lane = tx & 31;
    const long base = (long)blockIdx.x * 8;

    if (tx < 128) {
        int rl = tx >> 4, e = tx & 15;
        long g = (base + rl) * KOUT + e;
        s1v[tx] = g_tv[0][g];
        s1i[tx] = g_ti[0][g];
    } else {
        int t2 = tx - 128;
        int rl = t2 >> 4, e = t2 & 15;
        long g = (base + rl) * KOUT + e;
        s2v[t2] = g_tv[1][g];
        s2i[t2] = g_ti[1][g];
    }
    __syncthreads();

    const int row = warp;
    float v8[8];
    #pragma unroll
    for (int u = 0; u < 8; u++) {
        int f = lane + 32 * u;
        v8[u] = s1v[row * KOUT + (f >> 4)] + s2v[row * KOUT + (f & 15)];
    }
    float bmax = v8[0];
    int   bidx = 0;
    #pragma unroll
    for (int u = 1; u < 8; u++)
        if (v8[u] > bmax) { bmax = v8[u]; bidx = u; }

    long R = base + row;
    for (int r16 = 0; r16 < 16; r16++) {
        float wv = bmax;
        int   wi = lane + bidx * 32;
        #pragma unroll
        for (int o = 16; o; o >>= 1) {
            float ov = __shfl_xor_sync(0xffffffffu, wv, o);
            int   oi = __shfl_xor_sync(0xffffffffu, wi, o);
            if (ov > wv || (ov == wv && oi < wi)) { wv = ov; wi = oi; }
        }
        if (lane == 0) {
            int i16 = wi >> 4, j16 = wi & 15;
            int gidx = s1i[row * KOUT + i16] * NC + s2i[row * KOUT + j16];
            out[R * KOUT + r16]                      = (float)gidx;
            out[(long)NROWS * KOUT + R * KOUT + r16] = wv;
        }
        if ((wi & 31) == lane) v8[wi >> 5] = NEG_BIG;
        bmax = v8[0]; bidx = 0;
        #pragma unroll
        for (int u = 1; u < 8; u++)
            if (v8[u] > bmax) { bmax = v8[u]; bidx = u; }
    }
}

extern "C" void kernel_launch(void* const* d_in, const int* in_sizes, int n_in,
                              void* d_out, int out_size)
{
    const float* q     = (const float*)d_in[0];
    const float* ck    = (const float*)d_in[1];
    const float* cpk   = (const float*)d_in[2];
    const float* gamma = (const float*)d_in[3];
    const float* beta  = (const float*)d_in[4];
    float* out = (float*)d_out;

    cudaFuncSetAttribute(pkr_gemm,
                         cudaFuncAttributeMaxDynamicSharedMemorySize, SMEM_BYTES);

    pkr_transpose<<<dim3(4, 32, 2), dim3(32, 8)>>>(ck, cpk);
    pkr_gemm<<<(NROWS / TM) * 2, THREADS, SMEM_BYTES>>>(q, gamma, beta);
    pkr_joint<<<NROWS / 8, THREADS>>>(out);
}

// round 4
// speedup vs baseline: 1.8668x; 1.8668x over previous
#include <cuda_runtime.h>
#include <cuda_bf16.h>
#include <cstdint>

#define NROWS   65536       // 4*2048*8 query rows
#define D       256
#define SUB     128
#define NC      1024
#define KOUT    16
#define TM      16          // rows per gemm block
#define THREADS 512
#define NEG_BIG (-3.0e38f)

#define TILE_F  8192                         // 8 k x 1024 cols (floats)
#define OFF_CT  0                            // 2 x 32 KB
#define OFF_QN  (2 * TILE_F * 4)             // 65536
#define OFF_SC  (OFF_QN + TM * SUB * 4)      // 73728
#define SMEM_BYTES (OFF_SC + TM * NC * 4)    // 139264

// pre-swizzled centroids: [m][16 tiles][2048 16B-units]
__device__ float g_ct[2 * 16 * TILE_F];
__device__ float g_tv[2][NROWS * KOUT];
__device__ int   g_ti[2][NROWS * KOUT];

__device__ __forceinline__ void cp_async16(void* dst, const void* src) {
    uint32_t d32 = (uint32_t)__cvta_generic_to_shared(dst);
    asm volatile("cp.async.cg.shared.global [%0], [%1], 16;" :: "r"(d32), "l"(src));
}

// ---------------------------------------------------------------------------
// Kernel 0: rearrange C[1024][128] into swizzled k-tiled layout.
// For tile t, col c, s in {0,1}: unit u = (c*2+s) ^ ((c>>3)&7)
// holds C[c][t*8 + s*4 .. +3].
// grid 32 = m*16+t, 256 threads.
// ---------------------------------------------------------------------------
__global__ __launch_bounds__(256)
void pkr_prep(const float* __restrict__ ck, const float* __restrict__ cpk)
{
    const int m = blockIdx.x >> 4;
    const int t = blockIdx.x & 15;
    const float* C = m ? cpk : ck;
    float* dst = g_ct + m * 16 * TILE_F + t * TILE_F;
    for (int i = threadIdx.x; i < 2048; i += 256) {
        int c = i >> 1, s = i & 1;
        int u = i ^ ((i >> 4) & 7);
        *(float4*)&dst[u * 4] = *(const float4*)&C[c * SUB + t * 8 + s * 4];
    }
}

// ---------------------------------------------------------------------------
// Kernel 1: LN + per-subspace GEMM (16 x 1024 x 128) + per-row top-16
// grid = 8192: blockIdx>>1 = row tile, blockIdx&1 = subspace. 512 threads.
// ---------------------------------------------------------------------------
__global__ __launch_bounds__(THREADS, 1)
void pkr_gemm(const float* __restrict__ q,
              const float* __restrict__ gamma,
              const float* __restrict__ beta)
{
    extern __shared__ char smraw[];
    float* ct = (float*)(smraw + OFF_CT);
    float* qn = (float*)(smraw + OFF_QN);   // [row][128] local k
    float* sc = (float*)(smraw + OFF_SC);

    const int tx   = threadIdx.x;
    const int warp = tx >> 5;
    const int lane = tx & 31;
    const int m    = blockIdx.x & 1;
    const long base = (long)(blockIdx.x >> 1) * TM;

    const float* gsrc = g_ct + m * 16 * TILE_F;

    auto prefetch = [&](int t, int buf) {
        const float* src = gsrc + t * TILE_F;
        float* dst = ct + buf * TILE_F;
        #pragma unroll
        for (int i = 0; i < 4; i++) {
            int e = (tx + THREADS * i) * 4;
            cp_async16(dst + e, src + e);
        }
        asm volatile("cp.async.commit_group;");
    };

    prefetch(0, 0);
    prefetch(1, 1);

    // ---- LayerNorm: warp w handles row w; keep our 128-half in qn
    {
        const int row = warp;
        const float* qrow = q + (base + row) * D;
        float v[8];
        float s = 0.f, s2 = 0.f;
        #pragma unroll
        for (int i = 0; i < 8; i++) {
            v[i] = qrow[lane + 32 * i];
            s  += v[i];
            s2 += v[i] * v[i];
        }
        #pragma unroll
        for (int o = 16; o; o >>= 1) {
            s  += __shfl_xor_sync(0xffffffffu, s,  o);
            s2 += __shfl_xor_sync(0xffffffffu, s2, o);
        }
        float mu  = s * (1.f / D);
        float var = s2 * (1.f / D) - mu * mu;
        float inv = rsqrtf(var + 1e-5f);
        #pragma unroll
        for (int i = 0; i < 4; i++) {
            int ig = i + 4 * m;             // d = lane + 32*ig
            int d  = lane + 32 * ig;
            qn[row * SUB + (d - m * SUB)] =
                (v[ig] - mu) * inv * gamma[d] + beta[d];
        }
    }

    // ---- GEMM: thread tile 4 rows x 8 cols over full 1024 cols
    const int c_g = tx & 127;               // cols 8*c_g .. 8*c_g+7
    const int r_g = tx >> 7;                // rows 4*r_g .. 4*r_g+3
    const int sw  = c_g & 7;

    float acc[4][8];
    #pragma unroll
    for (int r = 0; r < 4; r++)
        #pragma unroll
        for (int j = 0; j < 8; j++) acc[r][j] = 0.f;

    for (int t = 0; t < 16; t++) {
        if (t < 14) {
            asm volatile("cp.async.wait_group 1;");
        } else {
            asm volatile("cp.async.wait_group 0;");
        }
        __syncthreads();

        const float4* ctb = (const float4*)(ct + (t & 1) * TILE_F);
        const float4* qn4 = (const float4*)qn;

        #pragma unroll
        for (int s = 0; s < 2; s++) {
            const int k4 = t * 2 + s;
            float4 qv[4];
            #pragma unroll
            for (int r = 0; r < 4; r++)
                qv[r] = qn4[(4 * r_g + r) * 32 + k4];
            #pragma unroll
            for (int j = 0; j < 8; j++) {
                const int c = 8 * c_g + j;
                float4 cc = ctb[(c * 2 + s) ^ sw];
                #pragma unroll
                for (int r = 0; r < 4; r++) {
                    acc[r][j] = fmaf(qv[r].x, cc.x, acc[r][j]);
                    acc[r][j] = fmaf(qv[r].y, cc.y, acc[r][j]);
                    acc[r][j] = fmaf(qv[r].z, cc.z, acc[r][j]);
                    acc[r][j] = fmaf(qv[r].w, cc.w, acc[r][j]);
                }
            }
        }
        __syncthreads();

        if (t < 14) prefetch(t + 2, t & 1);
    }

    // ---- write scores
    #pragma unroll
    for (int r = 0; r < 4; r++) {
        const int row = 4 * r_g + r;
        *(float4*)&sc[row * NC + 8 * c_g] =
            make_float4(acc[r][0], acc[r][1], acc[r][2], acc[r][3]);
        *(float4*)&sc[row * NC + 8 * c_g + 4] =
            make_float4(acc[r][4], acc[r][5], acc[r][6], acc[r][7]);
    }
    __syncthreads();

    // ---- per-row top-16 of 1024 (warp w: row w)
    {
        const int row = warp;
        float v[32];
        #pragma unroll
        for (int i = 0; i < 32; i++)
            v[i] = sc[row * NC + lane + 32 * i];

        float bmax = v[0];
        int   bidx = 0;
        #pragma unroll
        for (int i = 1; i < 32; i++)
            if (v[i] > bmax) { bmax = v[i]; bidx = i; }

        long gb = (base + row) * KOUT;
        for (int r16 = 0; r16 < 16; r16++) {
            float wv = bmax;
            int   wi = lane + bidx * 32;
            #pragma unroll
            for (int o = 16; o; o >>= 1) {
                float ov = __shfl_xor_sync(0xffffffffu, wv, o);
                int   oi = __shfl_xor_sync(0xffffffffu, wi, o);
                if (ov > wv || (ov == wv && oi < wi)) { wv = ov; wi = oi; }
            }
            if (lane == 0) { g_tv[m][gb + r16] = wv; g_ti[m][gb + r16] = wi; }
            if ((wi & 31) == lane) v[wi >> 5] = NEG_BIG;
            bmax = v[0]; bidx = 0;
            #pragma unroll
            for (int i = 1; i < 32; i++)
                if (v[i] > bmax) { bmax = v[i]; bidx = i; }
        }
    }
}

// ---------------------------------------------------------------------------
// Kernel 2: joint 16x16 top-16 + output. 8 rows/block, 1 row per warp.
// ---------------------------------------------------------------------------
__global__ __launch_bounds__(256, 1)
void pkr_joint(float* __restrict__ out)
{
    __shared__ float s1v[8 * KOUT], s2v[8 * KOUT];
    __shared__ int   s1i[8 * KOUT], s2i[8 * KOUT];

    const int tx   = threadIdx.x;
    const int warp = tx >> 5;
    const int lane = tx & 31;
    const long base = (long)blockIdx.x * 8;

    if (tx < 128) {
        long g = base * KOUT + tx;
        s1v[tx] = g_tv[0][g];
        s1i[tx] = g_ti[0][g];
    } else {
        int t2 = tx - 128;
        long g = base * KOUT + t2;
        s2v[t2] = g_tv[1][g];
        s2i[t2] = g_ti[1][g];
    }
    __syncthreads();

    const int row = warp;
    float v8[8];
    #pragma unroll
    for (int u = 0; u < 8; u++) {
        int f = lane + 32 * u;
        v8[u] = s1v[row * KOUT + (f >> 4)] + s2v[row * KOUT + (f & 15)];
    }
    float bmax = v8[0];
    int   bidx = 0;
    #pragma unroll
    for (int u = 1; u < 8; u++)
        if (v8[u] > bmax) { bmax = v8[u]; bidx = u; }

    long R = base + row;
    for (int r16 = 0; r16 < 16; r16++) {
        float wv = bmax;
        int   wi = lane + bidx * 32;
        #pragma unroll
        for (int o = 16; o; o >>= 1) {
            float ov = __shfl_xor_sync(0xffffffffu, wv, o);
            int   oi = __shfl_xor_sync(0xffffffffu, wi, o);
            if (ov > wv || (ov == wv && oi < wi)) { wv = ov; wi = oi; }
        }
        if (lane == 0) {
            int i16 = wi >> 4, j16 = wi & 15;
            int gidx = s1i[row * KOUT + i16] * NC + s2i[row * KOUT + j16];
            out[R * KOUT + r16]                      = (float)gidx;
            out[(long)NROWS * KOUT + R * KOUT + r16] = wv;
        }
        if ((wi & 31) == lane) v8[wi >> 5] = NEG_BIG;
        bmax = v8[0]; bidx = 0;
        #pragma unroll
        for (int u = 1; u < 8; u++)
            if (v8[u] > bmax) { bmax = v8[u]; bidx = u; }
    }
}

extern "C" void kernel_launch(void* const* d_in, const int* in_sizes, int n_in,
                              void* d_out, int out_size)
{
    const float* q     = (const float*)d_in[0];
    const float* ck    = (const float*)d_in[1];
    const float* cpk   = (const float*)d_in[2];
    const float* gamma = (const float*)d_in[3];
    const float* beta  = (const float*)d_in[4];
    float* out = (float*)d_out;

    cudaFuncSetAttribute(pkr_gemm,
                         cudaFuncAttributeMaxDynamicSharedMemorySize, SMEM_BYTES);

    pkr_prep<<<32, 256>>>(ck, cpk);
    pkr_gemm<<<(NROWS / TM) * 2, THREADS, SMEM_BYTES>>>(q, gamma, beta);
    pkr_joint<<<NROWS / 8, 256>>>(out);
}